// round 3
// baseline (speedup 1.0000x reference)
#include <cuda_runtime.h>
#include <cstdint>

// GraphSAGE 2-layer, mean aggregation.
// Strategy: transform-then-aggregate (mean-agg and linear commute):
//   y1 = x @ [W1_l; W1_r]^T            (one fused GEMM, N=128)
//   agg1[dst] += y1[src, 0:64]         (vector red.add) ; deg[dst] += 1
//   h = relu(agg1/max(deg,1) + b1 + y1[:, 64:128])
//   y2 = h @ [W2_l; W2_r]^T            (N=64)
//   agg2[dst] += y2[src, 0:32]
//   out = agg2/max(deg,1) + b2 + y2[:, 32:64]
//
// NOTE: reference edge_index is jnp.int64 but JAX x64 is disabled by default,
// so the buffer is int32 in practice. We auto-detect layout at runtime.

#define MAXN 100000
#define MAXE 1600000
#define DIN 128
#define DH 64
#define DOUT 32

// Scratch (no allocations allowed -> __device__ globals)
__device__ __align__(16) float g_y1[MAXN * (2 * DH)];   // [M][128]
__device__ __align__(16) float g_agg1[MAXN * DH];       // [M][64]
__device__ __align__(16) float g_h[MAXN * DH];          // [M][64]
__device__ __align__(16) float g_y2[MAXN * (2 * DOUT)]; // [M][64]
__device__ __align__(16) float g_agg2[MAXN * DOUT];     // [M][32]
__device__ __align__(16) float g_deg[MAXN];
__device__ __align__(16) int2  g_edge[MAXE];            // packed {src,dst}
__device__ int g_is64;

// ---------------------------------------------------------------------------
// Detect whether edge buffer is int64 (all odd 32-bit words of the first 128
// entries zero) or int32. Values are < 2^31 so int64 high words are 0.
// ---------------------------------------------------------------------------
__global__ void detect_kernel(const int* __restrict__ ei32, int nE) {
    int n = nE < 128 ? nE : 128;
    int ok = 1;
    for (int i = 0; i < n; i++)
        if (ei32[2 * i + 1] != 0) { ok = 0; break; }
    g_is64 = ok;
}

// ---------------------------------------------------------------------------
// Decode edges into packed int2 {src, dst}
// ---------------------------------------------------------------------------
__global__ __launch_bounds__(256) void decode_kernel(const void* __restrict__ ei,
                                                     int nE) {
    int e = blockIdx.x * blockDim.x + threadIdx.x;
    if (e >= nE) return;
    int src, dst;
    if (g_is64) {
        const long long* p = (const long long*)ei;
        src = (int)p[e];
        dst = (int)p[nE + e];
    } else {
        const int* p = (const int*)ei;
        src = p[e];
        dst = p[nE + e];
    }
    g_edge[e] = make_int2(src, dst);
}

// ---------------------------------------------------------------------------
// Zero the accumulators
// ---------------------------------------------------------------------------
__global__ __launch_bounds__(256) void zero_kernel(int M) {
    int idx = blockIdx.x * blockDim.x + threadIdx.x;
    const int n1 = M * 16;       // agg1 in float4
    const int n2 = M * 8;        // agg2 in float4
    const int n3 = M / 4;        // deg  in float4
    float4 z = make_float4(0.f, 0.f, 0.f, 0.f);
    if (idx < n1) {
        ((float4*)g_agg1)[idx] = z;
    } else if (idx < n1 + n2) {
        ((float4*)g_agg2)[idx - n1] = z;
    } else if (idx < n1 + n2 + n3) {
        ((float4*)g_deg)[idx - n1 - n2] = z;
    }
}

// ---------------------------------------------------------------------------
// Tiled fp32 GEMM: Y[M][BN] = X[M][K] @ [Wa; Wb]^T   (Wa = rows 0..BN/2)
// blockDim = (BM/TM)*(BN/TN). LAYER selects global in/out buffers.
// ---------------------------------------------------------------------------
template <int BM, int BN, int BK, int TM, int TN, int LAYER>
__global__ __launch_bounds__(256) void gemm_dual(const float* __restrict__ Xin,
                                                 const float* __restrict__ Wa,
                                                 const float* __restrict__ Wb,
                                                 int M, int K) {
    constexpr int NH = BN / 2;
    const float* __restrict__ X = (LAYER == 1) ? Xin : g_h;
    float* __restrict__ Y = (LAYER == 1) ? g_y1 : g_y2;

    __shared__ float Xs[BK][BM + 4];   // [k][m]
    __shared__ float Ws[BK][BN + 4];   // [k][n]

    const int tid = threadIdx.x;
    constexpr int TCOLS = BN / TN;
    const int tr = tid / TCOLS;
    const int tc = tid % TCOLS;
    const int m0 = blockIdx.x * BM;

    float acc[TM][TN];
#pragma unroll
    for (int i = 0; i < TM; i++)
#pragma unroll
        for (int j = 0; j < TN; j++) acc[i][j] = 0.f;

    for (int k0 = 0; k0 < K; k0 += BK) {
        // Load X tile [BM][BK] -> Xs[k][m]
        for (int i = tid * 4; i < BM * BK; i += blockDim.x * 4) {
            int r = i / BK;
            int c = i % BK;
            float4 v = make_float4(0.f, 0.f, 0.f, 0.f);
            if (m0 + r < M)
                v = *(const float4*)&X[(size_t)(m0 + r) * K + k0 + c];
            Xs[c + 0][r] = v.x; Xs[c + 1][r] = v.y;
            Xs[c + 2][r] = v.z; Xs[c + 3][r] = v.w;
        }
        // Load W tile [BN][BK] -> Ws[k][n] (row n<NH from Wa else Wb)
        for (int i = tid * 4; i < BN * BK; i += blockDim.x * 4) {
            int n = i / BK;
            int c = i % BK;
            const float* Wrow = (n < NH) ? (Wa + (size_t)n * K)
                                         : (Wb + (size_t)(n - NH) * K);
            float4 v = *(const float4*)&Wrow[k0 + c];
            Ws[c + 0][n] = v.x; Ws[c + 1][n] = v.y;
            Ws[c + 2][n] = v.z; Ws[c + 3][n] = v.w;
        }
        __syncthreads();

#pragma unroll
        for (int kk = 0; kk < BK; kk++) {
            float xr[TM], wr[TN];
#pragma unroll
            for (int i = 0; i < TM; i++) xr[i] = Xs[kk][tr * TM + i];
#pragma unroll
            for (int j = 0; j < TN; j++) wr[j] = Ws[kk][tc * TN + j];
#pragma unroll
            for (int i = 0; i < TM; i++)
#pragma unroll
                for (int j = 0; j < TN; j++)
                    acc[i][j] = fmaf(xr[i], wr[j], acc[i][j]);
        }
        __syncthreads();
    }

#pragma unroll
    for (int i = 0; i < TM; i++) {
        int m = m0 + tr * TM + i;
        if (m < M) {
#pragma unroll
            for (int j = 0; j < TN; j += 4) {
                float4 v = make_float4(acc[i][j], acc[i][j + 1],
                                       acc[i][j + 2], acc[i][j + 3]);
                *(float4*)&Y[(size_t)m * BN + tc * TN + j] = v;
            }
        }
    }
}

// ---------------------------------------------------------------------------
// Edge scatter: agg[dst] += y[src] via vector red.add (sm_90+).
// 16 threads/edge (layer1, 64 floats), 8 threads/edge (layer2, 32 floats).
// ---------------------------------------------------------------------------
__device__ __forceinline__ void red_add_f4(float4* p, float4 v) {
    asm volatile("red.global.add.v4.f32 [%0], {%1, %2, %3, %4};"
                 :: "l"(p), "f"(v.x), "f"(v.y), "f"(v.z), "f"(v.w)
                 : "memory");
}

__global__ __launch_bounds__(256) void scatter1(int nE) {
    int idx = blockIdx.x * blockDim.x + threadIdx.x;
    if (idx >= nE * 16) return;
    int e = idx >> 4;
    int c = idx & 15;
    int2 ed = __ldg(&g_edge[e]);
    float4 v = __ldg(((const float4*)g_y1) + (size_t)ed.x * 32 + c);  // cols 0..63
    red_add_f4(((float4*)g_agg1) + (size_t)ed.y * 16 + c, v);
    if (c == 0) atomicAdd(&g_deg[ed.y], 1.0f);
}

__global__ __launch_bounds__(256) void scatter2(int nE) {
    int idx = blockIdx.x * blockDim.x + threadIdx.x;
    if (idx >= nE * 8) return;
    int e = idx >> 3;
    int c = idx & 7;
    int2 ed = __ldg(&g_edge[e]);
    float4 v = __ldg(((const float4*)g_y2) + (size_t)ed.x * 16 + c);  // cols 0..31
    red_add_f4(((float4*)g_agg2) + (size_t)ed.y * 8 + c, v);
}

// ---------------------------------------------------------------------------
// h = relu(agg1/max(deg,1) + b1 + y1[:,64:128])
// ---------------------------------------------------------------------------
__global__ __launch_bounds__(256) void combine1(const float4* __restrict__ b1,
                                                int M) {
    int idx = blockIdx.x * blockDim.x + threadIdx.x;
    if (idx >= M * 16) return;
    int i = idx >> 4;
    int c = idx & 15;
    float inv = 1.0f / fmaxf(g_deg[i], 1.0f);
    float4 a = ((const float4*)g_agg1)[idx];
    float4 r = ((const float4*)g_y1)[(size_t)i * 32 + 16 + c];
    float4 b = __ldg(&b1[c]);
    float4 o;
    o.x = fmaxf(fmaf(a.x, inv, b.x + r.x), 0.f);
    o.y = fmaxf(fmaf(a.y, inv, b.y + r.y), 0.f);
    o.z = fmaxf(fmaf(a.z, inv, b.z + r.z), 0.f);
    o.w = fmaxf(fmaf(a.w, inv, b.w + r.w), 0.f);
    ((float4*)g_h)[idx] = o;
}

// ---------------------------------------------------------------------------
// out = agg2/max(deg,1) + b2 + y2[:,32:64]
// ---------------------------------------------------------------------------
__global__ __launch_bounds__(256) void final_kernel(const float4* __restrict__ b2,
                                                    float* __restrict__ out, int M) {
    int idx = blockIdx.x * blockDim.x + threadIdx.x;
    if (idx >= M * 8) return;
    int i = idx >> 3;
    int c = idx & 7;
    float inv = 1.0f / fmaxf(g_deg[i], 1.0f);
    float4 a = ((const float4*)g_agg2)[idx];
    float4 r = ((const float4*)g_y2)[(size_t)i * 16 + 8 + c];
    float4 b = __ldg(&b2[c]);
    float4 o;
    o.x = fmaf(a.x, inv, b.x + r.x);
    o.y = fmaf(a.y, inv, b.y + r.y);
    o.z = fmaf(a.z, inv, b.z + r.z);
    o.w = fmaf(a.w, inv, b.w + r.w);
    ((float4*)out)[idx] = o;
}

// ---------------------------------------------------------------------------
// Launch
// ---------------------------------------------------------------------------
static inline int cdiv(int a, int b) { return (a + b - 1) / b; }

extern "C" void kernel_launch(void* const* d_in, const int* in_sizes, int n_in,
                              void* d_out, int out_size) {
    const float* x    = (const float*)d_in[0];
    const void*  ei   = d_in[1];
    const float* W1l  = (const float*)d_in[2];
    const float* b1   = (const float*)d_in[3];
    const float* W1r  = (const float*)d_in[4];
    const float* W2l  = (const float*)d_in[5];
    const float* b2   = (const float*)d_in[6];
    const float* W2r  = (const float*)d_in[7];
    float* out = (float*)d_out;

    const int M  = in_sizes[0] / DIN;   // 100000
    const int nE = in_sizes[1] / 2;     // 1600000

    // 0. detect edge dtype + decode into packed int2
    detect_kernel<<<1, 1>>>((const int*)ei, nE);
    decode_kernel<<<cdiv(nE, 256), 256>>>(ei, nE);

    // 1. zero accumulators + deg
    {
        int tot = M * 16 + M * 8 + M / 4;
        zero_kernel<<<cdiv(tot, 256), 256>>>(M);
    }
    // 2. y1 = x @ [W1l; W1r]^T   (M x 128, K=128)
    gemm_dual<64, 128, 32, 4, 8, 1><<<cdiv(M, 64), 256>>>(x, W1l, W1r, M, DIN);
    // 3. agg1[dst] += y1[src,0:64]; deg[dst]++
    scatter1<<<cdiv(nE * 16, 256), 256>>>(nE);
    // 4. h = relu(agg1/deg + b1 + y1[:,64:128])
    combine1<<<cdiv(M * 16, 256), 256>>>((const float4*)b1, M);
    // 5. y2 = h @ [W2l; W2r]^T   (M x 64, K=64)
    gemm_dual<64, 64, 32, 4, 4, 2><<<cdiv(M, 64), 256>>>(nullptr, W2l, W2r, M, DH);
    // 6. agg2[dst] += y2[src,0:32]
    scatter2<<<cdiv(nE * 8, 256), 256>>>(nE);
    // 7. out = agg2/deg + b2 + y2[:,32:64]
    final_kernel<<<cdiv(M * 8, 256), 256>>>((const float4*)b2, out, M);
}

// round 6
// speedup vs baseline: 1.2175x; 1.2175x over previous
#include <cuda_runtime.h>
#include <cstdint>

// GraphSAGE 2-layer, mean aggregation. Transform-then-aggregate:
//   y1 = x @ [W1_l; W1_r]^T ; agg1[dst]+=y1[src,0:64]; deg[dst]++
//   h  = relu(agg1/max(deg,1) + b1 + y1[:,64:128])
//   y2 = h @ [W2_l; W2_r]^T ; agg2[dst]+=y2[src,0:32]
//   out= agg2/max(deg,1) + b2 + y2[:,32:64]
// edge_index dtype auto-detected (JAX x64-disabled => int32 in practice).

#define MAXN 100000
#define MAXE 1600000
#define DIN 128
#define DH 64
#define DOUT 32

__device__ __align__(16) float g_y1[MAXN * (2 * DH)];   // [M][128]
__device__ __align__(16) float g_agg1[MAXN * DH];       // [M][64]
__device__ __align__(16) float g_h[MAXN * DH];          // [M][64]
__device__ __align__(16) float g_y2[MAXN * (2 * DOUT)]; // [M][64]
__device__ __align__(16) float g_agg2[MAXN * DOUT];     // [M][32]
__device__ __align__(16) float g_deg[MAXN];
__device__ __align__(16) int2  g_edge[MAXE];
__device__ int g_is64;

// ---------------------------------------------------------------------------
__global__ void detect_kernel(const int* __restrict__ ei32, int nE) {
    int n = nE < 128 ? nE : 128;
    int ok = 1;
    for (int i = 0; i < n; i++)
        if (ei32[2 * i + 1] != 0) { ok = 0; break; }
    g_is64 = ok;
}

__global__ __launch_bounds__(256) void decode_kernel(const void* __restrict__ ei,
                                                     int nE) {
    int e = blockIdx.x * blockDim.x + threadIdx.x;
    if (e >= nE) return;
    int src, dst;
    if (g_is64) {
        const long long* p = (const long long*)ei;
        src = (int)p[e];
        dst = (int)p[nE + e];
    } else {
        const int* p = (const int*)ei;
        src = p[e];
        dst = p[nE + e];
    }
    g_edge[e] = make_int2(src, dst);
}

__global__ __launch_bounds__(256) void zero_kernel(int M) {
    int idx = blockIdx.x * blockDim.x + threadIdx.x;
    const int n1 = M * 16;
    const int n2 = M * 8;
    const int n3 = M / 4;
    float4 z = make_float4(0.f, 0.f, 0.f, 0.f);
    if (idx < n1) {
        ((float4*)g_agg1)[idx] = z;
    } else if (idx < n1 + n2) {
        ((float4*)g_agg2)[idx - n1] = z;
    } else if (idx < n1 + n2 + n3) {
        ((float4*)g_deg)[idx - n1 - n2] = z;
    }
}

// ---------------------------------------------------------------------------
// GEMM layer 1: Y[M][128] = X[M][128] @ [Wa(64x128); Wb(64x128)]^T
// BM=128, BN=128, BK=16. 256 threads, 8x8 split register tile.
// Per kk: 4 LDS.128 : 64 FMA, all LDS conflict-free.
// ---------------------------------------------------------------------------
__global__ __launch_bounds__(256, 2) void gemm1(const float* __restrict__ X,
                                                const float* __restrict__ Wa,
                                                const float* __restrict__ Wb,
                                                int M) {
    __shared__ float Xs[16][132];   // [k][m], 132*4=528 B row stride (16B-mult)
    __shared__ float Ws[16][132];   // [k][n]

    const int tid = threadIdx.x;
    const int m0 = blockIdx.x * 128;
    const int tr = tid >> 4;        // 0..15
    const int tc = tid & 15;        // 0..15
    const int lrow = tid >> 2;      // 0..63 (tile-load row)
    const int lc4 = (tid & 3) * 4;  // 0,4,8,12 (tile-load col)

    float acc[8][8];
#pragma unroll
    for (int i = 0; i < 8; i++)
#pragma unroll
        for (int j = 0; j < 8; j++) acc[i][j] = 0.f;

    for (int k0 = 0; k0 < 128; k0 += 16) {
        // X tile [128][16] -> Xs[k][m]
#pragma unroll
        for (int s = 0; s < 2; s++) {
            int r = lrow + s * 64;
            int gm = m0 + r;
            float4 v = make_float4(0.f, 0.f, 0.f, 0.f);
            if (gm < M) v = *(const float4*)&X[(size_t)gm * 128 + k0 + lc4];
            Xs[lc4 + 0][r] = v.x; Xs[lc4 + 1][r] = v.y;
            Xs[lc4 + 2][r] = v.z; Xs[lc4 + 3][r] = v.w;
        }
        // W tile [128][16] -> Ws[k][n]
#pragma unroll
        for (int s = 0; s < 2; s++) {
            int n = lrow + s * 64;
            const float* w = (n < 64) ? (Wa + (size_t)n * 128)
                                      : (Wb + (size_t)(n - 64) * 128);
            float4 v = *(const float4*)&w[k0 + lc4];
            Ws[lc4 + 0][n] = v.x; Ws[lc4 + 1][n] = v.y;
            Ws[lc4 + 2][n] = v.z; Ws[lc4 + 3][n] = v.w;
        }
        __syncthreads();

#pragma unroll
        for (int kk = 0; kk < 16; kk++) {
            float4 xa = *(const float4*)&Xs[kk][tr * 4];
            float4 xb = *(const float4*)&Xs[kk][64 + tr * 4];
            float4 wa = *(const float4*)&Ws[kk][tc * 4];
            float4 wb = *(const float4*)&Ws[kk][64 + tc * 4];
            float xv[8] = {xa.x, xa.y, xa.z, xa.w, xb.x, xb.y, xb.z, xb.w};
            float wv[8] = {wa.x, wa.y, wa.z, wa.w, wb.x, wb.y, wb.z, wb.w};
#pragma unroll
            for (int i = 0; i < 8; i++)
#pragma unroll
                for (int j = 0; j < 8; j++)
                    acc[i][j] = fmaf(xv[i], wv[j], acc[i][j]);
        }
        __syncthreads();
    }

#pragma unroll
    for (int si = 0; si < 2; si++)
#pragma unroll
        for (int i = 0; i < 4; i++) {
            int m = m0 + si * 64 + tr * 4 + i;
            if (m < M) {
#pragma unroll
                for (int sj = 0; sj < 2; sj++) {
                    int a = si * 4 + i;
                    float4 v = make_float4(acc[a][sj * 4 + 0], acc[a][sj * 4 + 1],
                                           acc[a][sj * 4 + 2], acc[a][sj * 4 + 3]);
                    *(float4*)&g_y1[(size_t)m * 128 + sj * 64 + tc * 4] = v;
                }
            }
        }
}

// ---------------------------------------------------------------------------
// GEMM layer 2: Y[M][64] = H[M][64] @ [Wa(32x64); Wb(32x64)]^T
// BM=128, BN=64, BK=16. 256 threads, 8x4 split register tile.
// ---------------------------------------------------------------------------
__global__ __launch_bounds__(256, 2) void gemm2(const float* __restrict__ Wa,
                                                const float* __restrict__ Wb,
                                                int M) {
    __shared__ float Xs[16][132];
    __shared__ float Ws[16][68];    // 68*4=272 B row stride (16B-mult)

    const int tid = threadIdx.x;
    const int m0 = blockIdx.x * 128;
    const int tr = tid >> 4;
    const int tc = tid & 15;
    const int lrow = tid >> 2;      // 0..63
    const int lc4 = (tid & 3) * 4;

    float acc[8][4];
#pragma unroll
    for (int i = 0; i < 8; i++)
#pragma unroll
        for (int j = 0; j < 4; j++) acc[i][j] = 0.f;

    for (int k0 = 0; k0 < 64; k0 += 16) {
        // H tile [128][16] -> Xs[k][m]
#pragma unroll
        for (int s = 0; s < 2; s++) {
            int r = lrow + s * 64;
            int gm = m0 + r;
            float4 v = make_float4(0.f, 0.f, 0.f, 0.f);
            if (gm < M) v = *(const float4*)&g_h[(size_t)gm * 64 + k0 + lc4];
            Xs[lc4 + 0][r] = v.x; Xs[lc4 + 1][r] = v.y;
            Xs[lc4 + 2][r] = v.z; Xs[lc4 + 3][r] = v.w;
        }
        // W tile [64][16] -> Ws[k][n]  (one float4 per thread)
        {
            int n = lrow;  // 0..63
            const float* w = (n < 32) ? (Wa + (size_t)n * 64)
                                      : (Wb + (size_t)(n - 32) * 64);
            float4 v = *(const float4*)&w[k0 + lc4];
            Ws[lc4 + 0][n] = v.x; Ws[lc4 + 1][n] = v.y;
            Ws[lc4 + 2][n] = v.z; Ws[lc4 + 3][n] = v.w;
        }
        __syncthreads();

#pragma unroll
        for (int kk = 0; kk < 16; kk++) {
            float4 xa = *(const float4*)&Xs[kk][tr * 4];
            float4 xb = *(const float4*)&Xs[kk][64 + tr * 4];
            float4 wa = *(const float4*)&Ws[kk][tc * 4];
            float xv[8] = {xa.x, xa.y, xa.z, xa.w, xb.x, xb.y, xb.z, xb.w};
            float wv[4] = {wa.x, wa.y, wa.z, wa.w};
#pragma unroll
            for (int i = 0; i < 8; i++)
#pragma unroll
                for (int j = 0; j < 4; j++)
                    acc[i][j] = fmaf(xv[i], wv[j], acc[i][j]);
        }
        __syncthreads();
    }

#pragma unroll
    for (int si = 0; si < 2; si++)
#pragma unroll
        for (int i = 0; i < 4; i++) {
            int m = m0 + si * 64 + tr * 4 + i;
            if (m < M) {
                int a = si * 4 + i;
                float4 v = make_float4(acc[a][0], acc[a][1], acc[a][2], acc[a][3]);
                *(float4*)&g_y2[(size_t)m * 64 + tc * 4] = v;
            }
        }
}

// ---------------------------------------------------------------------------
// Edge scatter via vector red.add (sm_90+).
// ---------------------------------------------------------------------------
__device__ __forceinline__ void red_add_f4(float4* p, float4 v) {
    asm volatile("red.global.add.v4.f32 [%0], {%1, %2, %3, %4};"
                 :: "l"(p), "f"(v.x), "f"(v.y), "f"(v.z), "f"(v.w)
                 : "memory");
}

__global__ __launch_bounds__(256) void scatter1(int nE) {
    int idx = blockIdx.x * blockDim.x + threadIdx.x;
    if (idx >= nE * 16) return;
    int e = idx >> 4;
    int c = idx & 15;
    int2 ed = __ldg(&g_edge[e]);
    float4 v = __ldg(((const float4*)g_y1) + (size_t)ed.x * 32 + c);
    red_add_f4(((float4*)g_agg1) + (size_t)ed.y * 16 + c, v);
    if (c == 0) atomicAdd(&g_deg[ed.y], 1.0f);
}

__global__ __launch_bounds__(256) void scatter2(int nE) {
    int idx = blockIdx.x * blockDim.x + threadIdx.x;
    if (idx >= nE * 8) return;
    int e = idx >> 3;
    int c = idx & 7;
    int2 ed = __ldg(&g_edge[e]);
    float4 v = __ldg(((const float4*)g_y2) + (size_t)ed.x * 16 + c);
    red_add_f4(((float4*)g_agg2) + (size_t)ed.y * 8 + c, v);
}

// ---------------------------------------------------------------------------
__global__ __launch_bounds__(256) void combine1(const float4* __restrict__ b1,
                                                int M) {
    int idx = blockIdx.x * blockDim.x + threadIdx.x;
    if (idx >= M * 16) return;
    int i = idx >> 4;
    int c = idx & 15;
    float inv = 1.0f / fmaxf(g_deg[i], 1.0f);
    float4 a = ((const float4*)g_agg1)[idx];
    float4 r = ((const float4*)g_y1)[(size_t)i * 32 + 16 + c];
    float4 b = __ldg(&b1[c]);
    float4 o;
    o.x = fmaxf(fmaf(a.x, inv, b.x + r.x), 0.f);
    o.y = fmaxf(fmaf(a.y, inv, b.y + r.y), 0.f);
    o.z = fmaxf(fmaf(a.z, inv, b.z + r.z), 0.f);
    o.w = fmaxf(fmaf(a.w, inv, b.w + r.w), 0.f);
    ((float4*)g_h)[idx] = o;
}

__global__ __launch_bounds__(256) void final_kernel(const float4* __restrict__ b2,
                                                    float* __restrict__ out, int M) {
    int idx = blockIdx.x * blockDim.x + threadIdx.x;
    if (idx >= M * 8) return;
    int i = idx >> 3;
    int c = idx & 7;
    float inv = 1.0f / fmaxf(g_deg[i], 1.0f);
    float4 a = ((const float4*)g_agg2)[idx];
    float4 r = ((const float4*)g_y2)[(size_t)i * 16 + 8 + c];
    float4 b = __ldg(&b2[c]);
    float4 o;
    o.x = fmaf(a.x, inv, b.x + r.x);
    o.y = fmaf(a.y, inv, b.y + r.y);
    o.z = fmaf(a.z, inv, b.z + r.z);
    o.w = fmaf(a.w, inv, b.w + r.w);
    ((float4*)out)[idx] = o;
}

// ---------------------------------------------------------------------------
static inline int cdiv(int a, int b) { return (a + b - 1) / b; }

extern "C" void kernel_launch(void* const* d_in, const int* in_sizes, int n_in,
                              void* d_out, int out_size) {
    const float* x    = (const float*)d_in[0];
    const void*  ei   = d_in[1];
    const float* W1l  = (const float*)d_in[2];
    const float* b1   = (const float*)d_in[3];
    const float* W1r  = (const float*)d_in[4];
    const float* W2l  = (const float*)d_in[5];
    const float* b2   = (const float*)d_in[6];
    const float* W2r  = (const float*)d_in[7];
    float* out = (float*)d_out;

    const int M  = in_sizes[0] / DIN;   // 100000
    const int nE = in_sizes[1] / 2;     // 1600000

    detect_kernel<<<1, 1>>>((const int*)ei, nE);
    decode_kernel<<<cdiv(nE, 256), 256>>>(ei, nE);
    {
        int tot = M * 16 + M * 8 + M / 4;
        zero_kernel<<<cdiv(tot, 256), 256>>>(M);
    }
    gemm1<<<cdiv(M, 128), 256>>>(x, W1l, W1r, M);
    scatter1<<<cdiv(nE * 16, 256), 256>>>(nE);
    combine1<<<cdiv(M * 16, 256), 256>>>((const float4*)b1, M);
    gemm2<<<cdiv(M, 128), 256>>>(W2l, W2r, M);
    scatter2<<<cdiv(nE * 8, 256), 256>>>(nE);
    final_kernel<<<cdiv(M * 8, 256), 256>>>((const float4*)b2, out, M);
}